// round 9
// baseline (speedup 1.0000x reference)
#include <cuda_runtime.h>
#include <cuda_bf16.h>
#include <cstdint>
#include <math.h>

#define SEQ    2048
#define DMODEL 2048

#define NEGINF (-1e30f)

// ---------------- scratch ----------------
__device__ float g_q[SEQ * 128];          // tanh(q proj)  [S][H*8]
__device__ float g_k[SEQ * 32];           // tanh(k proj)  [S][KV*8]
__device__ float g_v[SEQ * 32];           // sigmoid(v)    [S][KV*8]
__device__ float g_attn[SEQ * 128];       // affined attention out [S][H*8]
__device__ __nv_bfloat16 g_xh[SEQ * DMODEL];   // X hi
__device__ __nv_bfloat16 g_xl[SEQ * DMODEL];   // X lo
__device__ __nv_bfloat16 g_wh[192 * DMODEL];   // [Wq;Wk;Wv] hi
__device__ __nv_bfloat16 g_wl[192 * DMODEL];   // [Wq;Wk;Wv] lo

// attn dynamic smem layout (floats). G row stride = 101 (conflict-free prefix).
#define GSTR     101
#define QS_OFF   0
#define KS_OFF   768
#define VS_OFF   (768 + 1920)
#define G_OFF    (768 + 1920 + 1024)
#define SMEM_FLOATS (G_OFF + 96 * GSTR)   // 13408 floats = 53632 B

// ---------------- mma helpers ----------------
__device__ __forceinline__ uint32_t smem_u32(const void* p) {
    return (uint32_t)__cvta_generic_to_shared(p);
}
__device__ __forceinline__ void ldsm_x4(uint32_t r[4], uint32_t addr) {
    asm volatile("ldmatrix.sync.aligned.m8n8.x4.shared.b16 {%0,%1,%2,%3}, [%4];"
        : "=r"(r[0]), "=r"(r[1]), "=r"(r[2]), "=r"(r[3]) : "r"(addr));
}
__device__ __forceinline__ void mma_bf16(float c[4], const uint32_t a[4],
                                         uint32_t b0, uint32_t b1) {
    asm volatile("mma.sync.aligned.m16n8k16.row.col.f32.bf16.bf16.f32 "
        "{%0,%1,%2,%3},{%4,%5,%6,%7},{%8,%9},{%0,%1,%2,%3};"
        : "+f"(c[0]), "+f"(c[1]), "+f"(c[2]), "+f"(c[3])
        : "r"(a[0]), "r"(a[1]), "r"(a[2]), "r"(a[3]), "r"(b0), "r"(b1));
}

// ---------------- Pass A0: fp32 -> bf16 hi/lo split ----------------
__global__ __launch_bounds__(256) void convert_x(const float* __restrict__ X)
{
    const int i4 = (blockIdx.x * 256 + threadIdx.x) * 4;
    const float4 v = *(const float4*)(X + i4);
    const float xs[4] = {v.x, v.y, v.z, v.w};
    __nv_bfloat16 hs[4], ls[4];
    #pragma unroll
    for (int i = 0; i < 4; ++i) {
        hs[i] = __float2bfloat16(xs[i]);
        ls[i] = __float2bfloat16(xs[i] - __bfloat162float(hs[i]));
    }
    *(uint2*)&g_xh[i4] = *(uint2*)hs;
    *(uint2*)&g_xl[i4] = *(uint2*)ls;
}

__global__ __launch_bounds__(256) void convert_w(
    const float* __restrict__ Wq,
    const float* __restrict__ Wk,
    const float* __restrict__ Wv)
{
    const int i4 = (blockIdx.x * 256 + threadIdx.x) * 4;  // over 192*2048
    const int n = i4 >> 11, col = i4 & 2047;
    const float* src;
    if (n < 128)      src = Wq + (size_t)n * DMODEL;
    else if (n < 160) src = Wk + (size_t)(n - 128) * DMODEL;
    else              src = Wv + (size_t)(n - 160) * DMODEL;
    const float4 v = *(const float4*)(src + col);
    const float xs[4] = {v.x, v.y, v.z, v.w};
    __nv_bfloat16 hs[4], ls[4];
    #pragma unroll
    for (int i = 0; i < 4; ++i) {
        hs[i] = __float2bfloat16(xs[i]);
        ls[i] = __float2bfloat16(xs[i] - __bfloat162float(hs[i]));
    }
    *(uint2*)&g_wh[i4] = *(uint2*)hs;
    *(uint2*)&g_wl[i4] = *(uint2*)ls;
}

// ---------------- Pass A1: tensor-core QKV projection ----------------
#define PSTR 40
__global__ __launch_bounds__(256) void proj_mma(const float* __restrict__ tau)
{
    __shared__ __nv_bfloat16 sAh[2][64 * PSTR], sAl[2][64 * PSTR];
    __shared__ __nv_bfloat16 sBh[2][64 * PSTR], sBl[2][64 * PSTR];

    const int m0 = blockIdx.x * 64;
    const int n0 = blockIdx.y * 64;
    const int t  = threadIdx.x;
    const int w  = t >> 5, lane = t & 31;
    const int wm = (w & 3) * 16;
    const int wn = (w >> 2) * 32;
    const float inv_tau = 1.0f / tau[0];

    const int lrow = t >> 2;
    const int lcol = (t & 3) * 8;
    const size_t aoff0 = (size_t)(m0 + lrow) * DMODEL + lcol;
    const size_t boff0 = (size_t)(n0 + lrow) * DMODEL + lcol;
    const int sidx = lrow * PSTR + lcol;

    const int seg = lane >> 3, lr8 = lane & 7;
    const int a_r = wm + (seg & 1) * 8 + lr8;
    const int a_c0 = (seg >> 1) * 8;

    float acc[4][4] = {};

    uint4 pah = *(const uint4*)&g_xh[aoff0];
    uint4 pal = *(const uint4*)&g_xl[aoff0];
    uint4 pbh = *(const uint4*)&g_wh[boff0];
    uint4 pbl = *(const uint4*)&g_wl[boff0];

    for (int stage = 0; stage < 64; ++stage) {
        const int buf = stage & 1;
        __syncthreads();
        *(uint4*)&sAh[buf][sidx] = pah;
        *(uint4*)&sAl[buf][sidx] = pal;
        *(uint4*)&sBh[buf][sidx] = pbh;
        *(uint4*)&sBl[buf][sidx] = pbl;
        __syncthreads();
        if (stage + 1 < 64) {
            const size_t koff = (size_t)(stage + 1) * 32;
            pah = *(const uint4*)&g_xh[aoff0 + koff];
            pal = *(const uint4*)&g_xl[aoff0 + koff];
            pbh = *(const uint4*)&g_wh[boff0 + koff];
            pbl = *(const uint4*)&g_wl[boff0 + koff];
        }
        #pragma unroll
        for (int ks = 0; ks < 32; ks += 16) {
            uint32_t ah[4], al[4];
            {
                const int ac = ks + a_c0;
                ldsm_x4(ah, smem_u32(&sAh[buf][a_r * PSTR + ac]));
                ldsm_x4(al, smem_u32(&sAl[buf][a_r * PSTR + ac]));
            }
            #pragma unroll
            for (int nb = 0; nb < 32; nb += 16) {
                const int b_r = wn + nb + (seg >> 1) * 8 + lr8;
                const int b_c = ks + (seg & 1) * 8;
                uint32_t bh[4], bl[4];
                ldsm_x4(bh, smem_u32(&sBh[buf][b_r * PSTR + b_c]));
                ldsm_x4(bl, smem_u32(&sBl[buf][b_r * PSTR + b_c]));
                const int nt = nb >> 3;
                mma_bf16(acc[nt],     ah, bh[0], bh[1]);
                mma_bf16(acc[nt],     ah, bl[0], bl[1]);
                mma_bf16(acc[nt],     al, bh[0], bh[1]);
                mma_bf16(acc[nt + 1], ah, bh[2], bh[3]);
                mma_bf16(acc[nt + 1], ah, bl[2], bl[3]);
                mma_bf16(acc[nt + 1], al, bh[2], bh[3]);
            }
        }
    }

    const int group = lane >> 2, tg = lane & 3;
    #pragma unroll
    for (int nt = 0; nt < 4; ++nt) {
        const int n = n0 + wn + nt * 8 + tg * 2;
        const int m = m0 + wm + group;
        #pragma unroll
        for (int e = 0; e < 4; ++e) {
            const int mm = m + (e >> 1) * 8;
            const int nn = n + (e & 1);
            const float x = acc[nt][e] * inv_tau;
            if (nn < 128)      g_q[mm * 128 + nn]        = tanhf(x);
            else if (nn < 160) g_k[mm * 32 + (nn - 128)] = tanhf(x);
            else               g_v[mm * 32 + (nn - 160)] = 1.0f / (1.0f + expf(-x));
        }
    }
}

// ---------------- Pass B: fused suffix attention ----------------
// launch_bounds(256,3): cap regs at 84 -> 3 CTAs/SM (was 128 regs / 2 CTAs).
__global__ __launch_bounds__(256, 3) void attn_kernel(
    const float* __restrict__ tau,
    const float* __restrict__ ve0,
    const float* __restrict__ ve1)
{
    extern __shared__ float smem[];
    float* qs  = smem + QS_OFF;
    float* ksb = smem + KS_OFF;
    float* vsb = smem + VS_OFF;
    float* G   = smem + G_OFF;

    const int h  = blockIdx.y;
    const int qb = 31 - blockIdx.x;
    const int q0 = qb * 64;
    const int c  = h >> 2;
    const int t  = threadIdx.x;
    const float inv_tau = 1.0f / tau[0];
    const float scale   = 0.0625f * inv_tau;

    if (t < 192) {
        const int r = t >> 1, half = t & 1;
        const int gq = q0 - 31 + r;
        float4 v4 = make_float4(0.f, 0.f, 0.f, 0.f);
        if (gq >= 0 && gq < SEQ) v4 = *(const float4*)&g_q[gq * 128 + h * 8 + half * 4];
        *(float4*)&qs[r * 8 + half * 4] = v4;
    }

    const int a  = t >> 2;
    const int jq = t & 3;
    const int qg = q0 + a;
    const float bias_r = inv_tau / (float)(qg + 1);

    float m_run = NEGINF, l_run = 0.0f;
    float acc[8];
    #pragma unroll
    for (int d = 0; d < 8; ++d) acc[d] = 0.0f;

    const int ty = t >> 4, tx = t & 15;
    const int i0 = ty * 6, j0 = tx * 6;

    const int lr = t >> 1, lhalf = t & 1;
    const int lu = t - 192;

    {
        if (t < 192) {
            const int gk = -31 + lr;
            float4 v4 = make_float4(0.f, 0.f, 0.f, 0.f);
            if (gk >= 0) v4 = *(const float4*)&g_k[gk * 32 + c * 8 + lhalf * 4];
            float* p = &ksb[lr * 10 + lhalf * 4];
            *(float2*)(p)     = make_float2(v4.x, v4.y);
            *(float2*)(p + 2) = make_float2(v4.z, v4.w);
        } else {
            #pragma unroll
            for (int rep = 0; rep < 2; ++rep) {
                const int idx = lu * 2 + rep;
                const int r = idx >> 1, half = idx & 1;
                const int gk = r + 1;
                float4 v4 = *(const float4*)&g_v[gk * 32 + c * 8 + half * 4];
                *(float4*)&vsb[r * 8 + half * 4] = v4;
            }
        }
    }

    for (int kb = 0; kb <= qb; ++kb) {
        const int k0 = kb * 64;
        const int buf = kb & 1;
        const float* ks  = ksb + buf * 960;
        const float* vsm = vsb + buf * 512;
        __syncthreads();

        {
            float gacc[6][6] = {};
            #pragma unroll
            for (int dp = 0; dp < 4; ++dp) {
                float2 qd[6], kd[6];
                #pragma unroll
                for (int ii = 0; ii < 6; ++ii)
                    qd[ii] = *(const float2*)&qs[(i0 + ii) * 8 + dp * 2];
                #pragma unroll
                for (int jj = 0; jj < 6; ++jj)
                    kd[jj] = *(const float2*)&ks[(j0 + jj) * 10 + dp * 2];
                #pragma unroll
                for (int ii = 0; ii < 6; ++ii)
                    #pragma unroll
                    for (int jj = 0; jj < 6; ++jj) {
                        gacc[ii][jj] = fmaf(qd[ii].x, kd[jj].x, gacc[ii][jj]);
                        gacc[ii][jj] = fmaf(qd[ii].y, kd[jj].y, gacc[ii][jj]);
                    }
            }
            #pragma unroll
            for (int ii = 0; ii < 6; ++ii)
                #pragma unroll
                for (int jj = 0; jj < 6; ++jj)
                    G[(i0 + ii) * GSTR + (j0 + jj)] = gacc[ii][jj];
        }
        __syncthreads();

        if (t < 191) {
            const int dlt = t - 95;
            const int ad  = dlt < 0 ? -dlt : dlt;
            const int L   = 96 - ad;
            int off = (dlt > 0) ? dlt * GSTR : -dlt;
            float carry = 0.0f;
            int s = 0;
            for (; s + 4 <= L; s += 4) {
                const float e0 = G[off];
                const float e1 = G[off + (GSTR + 1)];
                const float e2 = G[off + 2 * (GSTR + 1)];
                const float e3 = G[off + 3 * (GSTR + 1)];
                const float c0 = carry + e0;
                const float c1 = c0 + e1;
                const float c2 = c1 + e2;
                const float c3 = c2 + e3;
                G[off] = c0;
                G[off + (GSTR + 1)]     = c1;
                G[off + 2 * (GSTR + 1)] = c2;
                G[off + 3 * (GSTR + 1)] = c3;
                carry = c3;
                off += 4 * (GSTR + 1);
            }
            for (; s < L; ++s) { carry += G[off]; G[off] = carry; off += GSTR + 1; }
        } else if (t >= 192 && kb < qb) {
            const int nk0 = k0 + 64;
            #pragma unroll
            for (int rep = 0; rep < 2; ++rep) {
                const int idx = lu * 2 + rep;
                const int r = idx >> 1, half = idx & 1;
                const int gk = nk0 + r + 1;
                float4 v4 = make_float4(0.f, 0.f, 0.f, 0.f);
                if (gk < SEQ) v4 = *(const float4*)&g_v[gk * 32 + c * 8 + half * 4];
                *(float4*)&vsb[(buf ^ 1) * 512 + r * 8 + half * 4] = v4;
            }
        }
        __syncthreads();

        if (kb < qb && t < 192) {
            const int gk = k0 + 64 - 31 + lr;
            const float4 v4 = *(const float4*)&g_k[gk * 32 + c * 8 + lhalf * 4];
            float* p = &ksb[(buf ^ 1) * 960 + lr * 10 + lhalf * 4];
            *(float2*)(p)     = make_float2(v4.x, v4.y);
            *(float2*)(p + 2) = make_float2(v4.z, v4.w);
        }

        float sv[16];
        float tmax = NEGINF;
        const int browH = (a + 31) * GSTR + 31;
        const int browL = (a - 1) * GSTR - 1;
        #pragma unroll
        for (int bb = 0; bb < 16; ++bb) {
            const int b  = (bb << 2) | jq;
            const int kg = k0 + b;
            float s = NEGINF;
            if (kg < qg) {
                const float hi = G[browH + b];
                const float lo = (a > 0 && b > 0) ? G[browL + b] : 0.0f;
                s = (hi - lo) * scale + (float)kg * bias_r;
            }
            sv[bb] = s;
            tmax = fmaxf(tmax, s);
        }
        if (tmax > NEGINF) {
            const float nm = fmaxf(m_run, tmax);
            if (m_run > NEGINF && nm > m_run) {
                const float f = __expf(m_run - nm);
                l_run *= f;
                #pragma unroll
                for (int d = 0; d < 8; ++d) acc[d] *= f;
            }
            m_run = nm;
            #pragma unroll
            for (int bb = 0; bb < 16; ++bb) {
                if (sv[bb] > NEGINF) {
                    const float e = __expf(sv[bb] - m_run);
                    l_run += e;
                    const int b = (bb << 2) | jq;
                    const float4 v0 = *(const float4*)&vsm[b * 8];
                    const float4 v1 = *(const float4*)&vsm[b * 8 + 4];
                    acc[0] = fmaf(e, v0.x, acc[0]); acc[1] = fmaf(e, v0.y, acc[1]);
                    acc[2] = fmaf(e, v0.z, acc[2]); acc[3] = fmaf(e, v0.w, acc[3]);
                    acc[4] = fmaf(e, v1.x, acc[4]); acc[5] = fmaf(e, v1.y, acc[5]);
                    acc[6] = fmaf(e, v1.z, acc[6]); acc[7] = fmaf(e, v1.w, acc[7]);
                }
            }
        }
    }

    #pragma unroll
    for (int off = 1; off < 4; off <<= 1) {
        const float mo  = __shfl_xor_sync(0xffffffffu, m_run, off);
        const float lo2 = __shfl_xor_sync(0xffffffffu, l_run, off);
        const float nm = fmaxf(m_run, mo);
        const float f1 = (m_run > NEGINF) ? __expf(m_run - nm) : 0.0f;
        const float f2 = (mo    > NEGINF) ? __expf(mo    - nm) : 0.0f;
        l_run = l_run * f1 + lo2 * f2;
        #pragma unroll
        for (int d = 0; d < 8; ++d) {
            const float ao = __shfl_xor_sync(0xffffffffu, acc[d], off);
            acc[d] = acc[d] * f1 + ao * f2;
        }
        m_run = nm;
    }
    if (jq == 0) {
        const float invl = (l_run > 0.0f) ? 1.0f / l_run : 0.0f;
        #pragma unroll
        for (int d = 0; d < 8; ++d) {
            const int f = h * 8 + d;
            const float e0 = ve0[f], e1 = ve1[f];
            const float o  = acc[d] * invl;
            g_attn[qg * 128 + f] = o * (e1 - e0) + e0;
        }
    }
}

// ---------------- Pass C: output projection (unchanged) ----------------
__global__ __launch_bounds__(256) void out_kernel(
    const float* __restrict__ Wo,
    float* __restrict__ out)
{
    __shared__ float As[16][132];
    __shared__ float Bs[16][68];
    const int m0 = blockIdx.x * 128;
    const int n0 = blockIdx.y * 64;
    const int t  = threadIdx.x;

    const int arow = t >> 1;
    const int akA  = (t & 1) * 4;
    const int brow = t >> 2;
    const int bk   = (t & 3) * 4;
    const float* ar_ = g_attn + (size_t)(m0 + arow) * 128;
    const float* br_ = Wo + (size_t)(n0 + brow) * 128;

    const int tyy = t >> 4, txx = t & 15;
    const int i0 = tyy * 8, j0 = txx * 4;

    float4 a0 = *(const float4*)(ar_ + akA);
    float4 a1 = *(const float4*)(ar_ + akA + 8);
    float4 b0 = *(const float4*)(br_ + bk);

    float acc[8][4] = {};
    for (int k0 = 0; k0 < 128; k0 += 16) {
        __syncthreads();
        As[akA + 0][arow] = a0.x; As[akA + 1][arow] = a0.y;
        As[akA + 2][arow] = a0.z; As[akA + 3][arow] = a0.w;
        As[akA + 8][arow] = a1.x; As[akA + 9][arow] = a1.y;
        As[akA +10][arow] = a1.z; As[akA +11][arow] = a1.w;
        Bs[bk + 0][brow] = b0.x; Bs[bk + 1][brow] = b0.y;
        Bs[bk + 2][brow] = b0.z; Bs[bk + 3][brow] = b0.w;
        __syncthreads();
        if (k0 + 16 < 128) {
            a0 = *(const float4*)(ar_ + k0 + 16 + akA);
            a1 = *(const float4*)(ar_ + k0 + 16 + akA + 8);
            b0 = *(const float4*)(br_ + k0 + 16 + bk);
        }
        #pragma unroll
        for (int kk = 0; kk < 16; ++kk) {
            const float4 av0 = *(const float4*)&As[kk][i0];
            const float4 av1 = *(const float4*)&As[kk][i0 + 4];
            const float4 bv  = *(const float4*)&Bs[kk][j0];
            float ar[8] = {av0.x, av0.y, av0.z, av0.w, av1.x, av1.y, av1.z, av1.w};
            float br[4] = {bv.x, bv.y, bv.z, bv.w};
            #pragma unroll
            for (int i = 0; i < 8; ++i)
                #pragma unroll
                for (int j = 0; j < 4; ++j)
                    acc[i][j] = fmaf(ar[i], br[j], acc[i][j]);
        }
    }
    #pragma unroll
    for (int i = 0; i < 8; ++i) {
        float4 o = make_float4(acc[i][0], acc[i][1], acc[i][2], acc[i][3]);
        *(float4*)&out[(size_t)(m0 + i0 + i) * DMODEL + n0 + j0] = o;
    }
}

// ---------------- launch ----------------
extern "C" void kernel_launch(void* const* d_in, const int* in_sizes, int n_in,
                              void* d_out, int out_size)
{
    const float* X   = (const float*)d_in[0];
    const float* Wq  = (const float*)d_in[1];
    const float* Wk  = (const float*)d_in[2];
    const float* Wv  = (const float*)d_in[3];
    const float* Wo  = (const float*)d_in[4];
    const float* ve0 = (const float*)d_in[5];
    const float* ve1 = (const float*)d_in[6];
    const float* tau = (const float*)d_in[7];
    float* out = (float*)d_out;
    (void)in_sizes; (void)n_in; (void)out_size;

    cudaFuncSetAttribute(attn_kernel,
                         cudaFuncAttributeMaxDynamicSharedMemorySize,
                         SMEM_FLOATS * (int)sizeof(float));

    convert_x <<<4096, 256>>>(X);
    convert_w <<<384, 256>>>(Wq, Wk, Wv);
    proj_mma  <<<dim3(32, 3), 256>>>(tau);
    attn_kernel<<<dim3(32, 16), 256, SMEM_FLOATS * sizeof(float)>>>(tau, ve0, ve1);
    out_kernel <<<dim3(16, 32), 256>>>(Wo, out);
}

// round 10
// speedup vs baseline: 1.0876x; 1.0876x over previous
#include <cuda_runtime.h>
#include <cuda_bf16.h>
#include <cstdint>
#include <math.h>

#define SEQ    2048
#define DMODEL 2048

#define NEGINF (-1e30f)

// ---------------- scratch ----------------
__device__ float g_v[SEQ * 32];                // sigmoid(v)  [S][KV*8]
__device__ float g_attn[SEQ * 128];            // affined attention out [S][H*8]
__device__ __nv_bfloat16 g_qh[SEQ * 128];      // tanh(q) hi
__device__ __nv_bfloat16 g_ql[SEQ * 128];      // tanh(q) lo
__device__ __nv_bfloat16 g_kh[SEQ * 32];       // tanh(k) hi
__device__ __nv_bfloat16 g_kl[SEQ * 32];       // tanh(k) lo
__device__ __nv_bfloat16 g_xh[SEQ * DMODEL];   // X hi
__device__ __nv_bfloat16 g_xl[SEQ * DMODEL];   // X lo
__device__ __nv_bfloat16 g_wh[192 * DMODEL];   // [Wq;Wk;Wv] hi
__device__ __nv_bfloat16 g_wl[192 * DMODEL];   // [Wq;Wk;Wv] lo

// attn dynamic smem layout (float units). G row stride 101:
// diagonal-prefix lane stride 101 == 5 (mod 32) -> conflict-free.
#define GSTR     101
#define QHS_OFF  0                         // 96 rows x 16B bf16 hi  = 384 fl
#define QLS_OFF  384                       // lo                      = 384
#define KHS_OFF  768                       // 2 bufs x 384            = 768
#define KLS_OFF  1536                      // 2 bufs x 384            = 768
#define VS_OFF   2304                      // 2 x 64 x 8 fp32         = 1024
#define G_OFF    3328                      // 96*101                  = 9696
#define SMEM_FLOATS (G_OFF + 96 * GSTR)    // 13024 floats = 52096 B

// ---------------- mma helpers ----------------
__device__ __forceinline__ uint32_t smem_u32(const void* p) {
    return (uint32_t)__cvta_generic_to_shared(p);
}
__device__ __forceinline__ void ldsm_x4(uint32_t r[4], uint32_t addr) {
    asm volatile("ldmatrix.sync.aligned.m8n8.x4.shared.b16 {%0,%1,%2,%3}, [%4];"
        : "=r"(r[0]), "=r"(r[1]), "=r"(r[2]), "=r"(r[3]) : "r"(addr));
}
__device__ __forceinline__ void mma_bf16(float c[4], const uint32_t a[4],
                                         uint32_t b0, uint32_t b1) {
    asm volatile("mma.sync.aligned.m16n8k16.row.col.f32.bf16.bf16.f32 "
        "{%0,%1,%2,%3},{%4,%5,%6,%7},{%8,%9},{%0,%1,%2,%3};"
        : "+f"(c[0]), "+f"(c[1]), "+f"(c[2]), "+f"(c[3])
        : "r"(a[0]), "r"(a[1]), "r"(a[2]), "r"(a[3]), "r"(b0), "r"(b1));
}
__device__ __forceinline__ void mma_k8(float c[4], uint32_t a0, uint32_t a1,
                                       uint32_t b) {
    asm volatile("mma.sync.aligned.m16n8k8.row.col.f32.bf16.bf16.f32 "
        "{%0,%1,%2,%3},{%4,%5},{%6},{%0,%1,%2,%3};"
        : "+f"(c[0]), "+f"(c[1]), "+f"(c[2]), "+f"(c[3])
        : "r"(a0), "r"(a1), "r"(b));
}

// ---------------- Pass A0: fp32 -> bf16 hi/lo split ----------------
__global__ __launch_bounds__(256) void convert_x(const float* __restrict__ X)
{
    const int i4 = (blockIdx.x * 256 + threadIdx.x) * 4;
    const float4 v = *(const float4*)(X + i4);
    const float xs[4] = {v.x, v.y, v.z, v.w};
    __nv_bfloat16 hs[4], ls[4];
    #pragma unroll
    for (int i = 0; i < 4; ++i) {
        hs[i] = __float2bfloat16(xs[i]);
        ls[i] = __float2bfloat16(xs[i] - __bfloat162float(hs[i]));
    }
    *(uint2*)&g_xh[i4] = *(uint2*)hs;
    *(uint2*)&g_xl[i4] = *(uint2*)ls;
}

__global__ __launch_bounds__(256) void convert_w(
    const float* __restrict__ Wq,
    const float* __restrict__ Wk,
    const float* __restrict__ Wv)
{
    const int i4 = (blockIdx.x * 256 + threadIdx.x) * 4;
    const int n = i4 >> 11, col = i4 & 2047;
    const float* src;
    if (n < 128)      src = Wq + (size_t)n * DMODEL;
    else if (n < 160) src = Wk + (size_t)(n - 128) * DMODEL;
    else              src = Wv + (size_t)(n - 160) * DMODEL;
    const float4 v = *(const float4*)(src + col);
    const float xs[4] = {v.x, v.y, v.z, v.w};
    __nv_bfloat16 hs[4], ls[4];
    #pragma unroll
    for (int i = 0; i < 4; ++i) {
        hs[i] = __float2bfloat16(xs[i]);
        ls[i] = __float2bfloat16(xs[i] - __bfloat162float(hs[i]));
    }
    *(uint2*)&g_wh[i4] = *(uint2*)hs;
    *(uint2*)&g_wl[i4] = *(uint2*)ls;
}

// ---------------- Pass A1: tensor-core QKV projection ----------------
#define PSTR 40
__global__ __launch_bounds__(256) void proj_mma(const float* __restrict__ tau)
{
    __shared__ __nv_bfloat16 sAh[2][64 * PSTR], sAl[2][64 * PSTR];
    __shared__ __nv_bfloat16 sBh[2][64 * PSTR], sBl[2][64 * PSTR];

    const int m0 = blockIdx.x * 64;
    const int n0 = blockIdx.y * 64;
    const int t  = threadIdx.x;
    const int w  = t >> 5, lane = t & 31;
    const int wm = (w & 3) * 16;
    const int wn = (w >> 2) * 32;
    const float inv_tau = 1.0f / tau[0];

    const int lrow = t >> 2;
    const int lcol = (t & 3) * 8;
    const size_t aoff0 = (size_t)(m0 + lrow) * DMODEL + lcol;
    const size_t boff0 = (size_t)(n0 + lrow) * DMODEL + lcol;
    const int sidx = lrow * PSTR + lcol;

    const int seg = lane >> 3, lr8 = lane & 7;
    const int a_r = wm + (seg & 1) * 8 + lr8;
    const int a_c0 = (seg >> 1) * 8;

    float acc[4][4] = {};

    uint4 pah = *(const uint4*)&g_xh[aoff0];
    uint4 pal = *(const uint4*)&g_xl[aoff0];
    uint4 pbh = *(const uint4*)&g_wh[boff0];
    uint4 pbl = *(const uint4*)&g_wl[boff0];

    for (int stage = 0; stage < 64; ++stage) {
        const int buf = stage & 1;
        __syncthreads();
        *(uint4*)&sAh[buf][sidx] = pah;
        *(uint4*)&sAl[buf][sidx] = pal;
        *(uint4*)&sBh[buf][sidx] = pbh;
        *(uint4*)&sBl[buf][sidx] = pbl;
        __syncthreads();
        if (stage + 1 < 64) {
            const size_t koff = (size_t)(stage + 1) * 32;
            pah = *(const uint4*)&g_xh[aoff0 + koff];
            pal = *(const uint4*)&g_xl[aoff0 + koff];
            pbh = *(const uint4*)&g_wh[boff0 + koff];
            pbl = *(const uint4*)&g_wl[boff0 + koff];
        }
        #pragma unroll
        for (int ks = 0; ks < 32; ks += 16) {
            uint32_t ah[4], al[4];
            {
                const int ac = ks + a_c0;
                ldsm_x4(ah, smem_u32(&sAh[buf][a_r * PSTR + ac]));
                ldsm_x4(al, smem_u32(&sAl[buf][a_r * PSTR + ac]));
            }
            #pragma unroll
            for (int nb = 0; nb < 32; nb += 16) {
                const int b_r = wn + nb + (seg >> 1) * 8 + lr8;
                const int b_c = ks + (seg & 1) * 8;
                uint32_t bh[4], bl[4];
                ldsm_x4(bh, smem_u32(&sBh[buf][b_r * PSTR + b_c]));
                ldsm_x4(bl, smem_u32(&sBl[buf][b_r * PSTR + b_c]));
                const int nt = nb >> 3;
                mma_bf16(acc[nt],     ah, bh[0], bh[1]);
                mma_bf16(acc[nt],     ah, bl[0], bl[1]);
                mma_bf16(acc[nt],     al, bh[0], bh[1]);
                mma_bf16(acc[nt + 1], ah, bh[2], bh[3]);
                mma_bf16(acc[nt + 1], ah, bl[2], bl[3]);
                mma_bf16(acc[nt + 1], al, bh[2], bh[3]);
            }
        }
    }

    // epilogue: activations; q/k also split to bf16 hi/lo for attn's MMA
    const int group = lane >> 2, tg = lane & 3;
    #pragma unroll
    for (int nt = 0; nt < 4; ++nt) {
        const int n = n0 + wn + nt * 8 + tg * 2;
        const int m = m0 + wm + group;
        #pragma unroll
        for (int e = 0; e < 4; ++e) {
            const int mm = m + (e >> 1) * 8;
            const int nn = n + (e & 1);
            const float x = acc[nt][e] * inv_tau;
            if (nn < 160) {
                const float tv = tanhf(x);
                const __nv_bfloat16 th = __float2bfloat16(tv);
                const __nv_bfloat16 tl = __float2bfloat16(tv - __bfloat162float(th));
                if (nn < 128) { g_qh[mm * 128 + nn] = th; g_ql[mm * 128 + nn] = tl; }
                else { g_kh[mm * 32 + (nn - 128)] = th; g_kl[mm * 32 + (nn - 128)] = tl; }
            } else {
                g_v[mm * 32 + (nn - 160)] = 1.0f / (1.0f + expf(-x));
            }
        }
    }
}

// ---------------- Pass B: fused suffix attention (G via m16n8k8 MMA) ----------------
__global__ __launch_bounds__(256, 3) void attn_kernel(
    const float* __restrict__ tau,
    const float* __restrict__ ve0,
    const float* __restrict__ ve1)
{
    extern __shared__ float smem[];
    const uint32_t* qh32 = (const uint32_t*)(smem + QHS_OFF);  // [96][4] u32 (bf16x2)
    const uint32_t* ql32 = (const uint32_t*)(smem + QLS_OFF);
    float* vsb = smem + VS_OFF;
    float* G   = smem + G_OFF;

    const int h  = blockIdx.y;
    const int qb = 31 - blockIdx.x;
    const int q0 = qb * 64;
    const int c  = h >> 2;
    const int t  = threadIdx.x;
    const int w  = t >> 5, lane = t & 31;
    const float inv_tau = 1.0f / tau[0];
    const float scale   = 0.0625f * inv_tau;

    // q halo: rows q0-31 .. q0+64, bf16 hi/lo (16B per row each)
    if (t < 192) {
        const int r = t >> 1, half = t & 1;
        const int gq = q0 - 31 + r;
        uint4 v4 = make_uint4(0u, 0u, 0u, 0u);
        const __nv_bfloat16* src = half ? g_ql : g_qh;
        if (gq >= 0 && gq < SEQ) v4 = *(const uint4*)&src[gq * 128 + h * 8];
        float* dst = smem + (half ? QLS_OFF : QHS_OFF);
        *(uint4*)&dst[r * 4] = v4;
    }

    const int a  = t >> 2;
    const int jq = t & 3;
    const int qg = q0 + a;
    const float bias_r = inv_tau / (float)(qg + 1);

    float m_run = NEGINF, l_run = 0.0f;
    float acc[8];
    #pragma unroll
    for (int d = 0; d < 8; ++d) acc[d] = 0.0f;

    // mma fragment lane mapping
    const int fr = lane >> 2;          // 0..7
    const int fq = lane & 3;           // col-pair index
    const int fc = fq * 2;

    // loader mapping
    const int lr = t >> 1, lhalf = t & 1;   // t < 192: k halo hi/lo
    const int lu = t - 192;                 // t >= 192: v rows

    // ---- preload tile 0 into buffer 0 ----
    {
        if (t < 192) {
            const int gk = -31 + lr;
            uint4 v4 = make_uint4(0u, 0u, 0u, 0u);
            const __nv_bfloat16* src = lhalf ? g_kl : g_kh;
            if (gk >= 0) v4 = *(const uint4*)&src[gk * 32 + c * 8];
            float* dst = smem + (lhalf ? KLS_OFF : KHS_OFF);
            *(uint4*)&dst[lr * 4] = v4;
        } else {
            #pragma unroll
            for (int rep = 0; rep < 2; ++rep) {
                const int idx = lu * 2 + rep;
                const int r = idx >> 1, half = idx & 1;
                const int gk = r + 1;
                float4 v4 = *(const float4*)&g_v[gk * 32 + c * 8 + half * 4];
                *(float4*)&vsb[r * 8 + half * 4] = v4;
            }
        }
    }

    for (int kb = 0; kb <= qb; ++kb) {
        const int k0 = kb * 64;
        const int buf = kb & 1;
        const uint32_t* kh32 = (const uint32_t*)(smem + KHS_OFF + buf * 384);
        const uint32_t* kl32 = (const uint32_t*)(smem + KLS_OFF + buf * 384);
        const float* vsm = vsb + buf * 512;
        __syncthreads();   // loads done; prev score done with G

        // ---- G = qhalo(96x8) . khalo(96x8)^T via m16n8k8, hi/lo 3x ----
        // 6 m-tiles x 12 n-tiles = 72 positions; warp w does p = w + 8k.
        #pragma unroll
        for (int k9 = 0; k9 < 9; ++k9) {
            const int p  = w + (k9 << 3);
            const int mt = p / 12;
            const int nt = p - mt * 12;
            const int ai = (mt * 16 + fr) * 4 + fq;
            const uint32_t ah0 = qh32[ai],      ah1 = qh32[ai + 32];
            const uint32_t al0 = ql32[ai],      al1 = ql32[ai + 32];
            const int bi = (nt * 8 + fr) * 4 + fq;
            const uint32_t bh = kh32[bi], bl = kl32[bi];
            float cfr[4] = {0.f, 0.f, 0.f, 0.f};
            mma_k8(cfr, ah0, ah1, bh);
            mma_k8(cfr, ah0, ah1, bl);
            mma_k8(cfr, al0, al1, bh);
            float* gp = &G[(mt * 16 + fr) * GSTR + nt * 8 + fc];
            gp[0] = cfr[0]; gp[1] = cfr[1];
            gp[8 * GSTR] = cfr[2]; gp[8 * GSTR + 1] = cfr[3];
        }
        __syncthreads();

        // ---- diagonal prefix (threads 0..190); v-prefetch (192..255) ----
        if (t < 191) {
            const int dlt = t - 95;
            const int ad  = dlt < 0 ? -dlt : dlt;
            const int L   = 96 - ad;
            int off = (dlt > 0) ? dlt * GSTR : -dlt;
            float carry = 0.0f;
            int s = 0;
            for (; s + 4 <= L; s += 4) {
                const float e0 = G[off];
                const float e1 = G[off + (GSTR + 1)];
                const float e2 = G[off + 2 * (GSTR + 1)];
                const float e3 = G[off + 3 * (GSTR + 1)];
                const float c0 = carry + e0;
                const float c1 = c0 + e1;
                const float c2 = c1 + e2;
                const float c3 = c2 + e3;
                G[off] = c0;
                G[off + (GSTR + 1)]     = c1;
                G[off + 2 * (GSTR + 1)] = c2;
                G[off + 3 * (GSTR + 1)] = c3;
                carry = c3;
                off += 4 * (GSTR + 1);
            }
            for (; s < L; ++s) { carry += G[off]; G[off] = carry; off += GSTR + 1; }
        } else if (t >= 192 && kb < qb) {
            const int nk0 = k0 + 64;
            #pragma unroll
            for (int rep = 0; rep < 2; ++rep) {
                const int idx = lu * 2 + rep;
                const int r = idx >> 1, half = idx & 1;
                const int gk = nk0 + r + 1;
                float4 v4 = make_float4(0.f, 0.f, 0.f, 0.f);
                if (gk < SEQ) v4 = *(const float4*)&g_v[gk * 32 + c * 8 + half * 4];
                *(float4*)&vsb[(buf ^ 1) * 512 + r * 8 + half * 4] = v4;
            }
        }
        __syncthreads();

        // ---- k-halo prefetch for next tile (overlaps score phase) ----
        if (kb < qb && t < 192) {
            const int gk = k0 + 64 - 31 + lr;
            const __nv_bfloat16* src = lhalf ? g_kl : g_kh;
            const uint4 v4 = *(const uint4*)&src[gk * 32 + c * 8];
            float* dst = smem + (lhalf ? KLS_OFF : KHS_OFF) + (buf ^ 1) * 384;
            *(uint4*)&dst[lr * 4] = v4;
        }

        // ---- scores + single-pass online softmax ----
        float sv[16];
        float tmax = NEGINF;
        const int browH = (a + 31) * GSTR + 31;
        const int browL = (a - 1) * GSTR - 1;
        #pragma unroll
        for (int bb = 0; bb < 16; ++bb) {
            const int b  = (bb << 2) | jq;
            const int kg = k0 + b;
            float s = NEGINF;
            if (kg < qg) {
                const float hi = G[browH + b];
                const float lo = (a > 0 && b > 0) ? G[browL + b] : 0.0f;
                s = (hi - lo) * scale + (float)kg * bias_r;
            }
            sv[bb] = s;
            tmax = fmaxf(tmax, s);
        }
        if (tmax > NEGINF) {
            const float nm = fmaxf(m_run, tmax);
            if (m_run > NEGINF && nm > m_run) {
                const float f = __expf(m_run - nm);
                l_run *= f;
                #pragma unroll
                for (int d = 0; d < 8; ++d) acc[d] *= f;
            }
            m_run = nm;
            #pragma unroll
            for (int bb = 0; bb < 16; ++bb) {
                if (sv[bb] > NEGINF) {
                    const float e = __expf(sv[bb] - m_run);
                    l_run += e;
                    const int b = (bb << 2) | jq;
                    const float4 v0 = *(const float4*)&vsm[b * 8];
                    const float4 v1 = *(const float4*)&vsm[b * 8 + 4];
                    acc[0] = fmaf(e, v0.x, acc[0]); acc[1] = fmaf(e, v0.y, acc[1]);
                    acc[2] = fmaf(e, v0.z, acc[2]); acc[3] = fmaf(e, v0.w, acc[3]);
                    acc[4] = fmaf(e, v1.x, acc[4]); acc[5] = fmaf(e, v1.y, acc[5]);
                    acc[6] = fmaf(e, v1.z, acc[6]); acc[7] = fmaf(e, v1.w, acc[7]);
                }
            }
        }
    }

    // merge the 4 threads of each query row
    #pragma unroll
    for (int off = 1; off < 4; off <<= 1) {
        const float mo  = __shfl_xor_sync(0xffffffffu, m_run, off);
        const float lo2 = __shfl_xor_sync(0xffffffffu, l_run, off);
        const float nm = fmaxf(m_run, mo);
        const float f1 = (m_run > NEGINF) ? __expf(m_run - nm) : 0.0f;
        const float f2 = (mo    > NEGINF) ? __expf(mo    - nm) : 0.0f;
        l_run = l_run * f1 + lo2 * f2;
        #pragma unroll
        for (int d = 0; d < 8; ++d) {
            const float ao = __shfl_xor_sync(0xffffffffu, acc[d], off);
            acc[d] = acc[d] * f1 + ao * f2;
        }
        m_run = nm;
    }
    if (jq == 0) {
        const float invl = (l_run > 0.0f) ? 1.0f / l_run : 0.0f;
        #pragma unroll
        for (int d = 0; d < 8; ++d) {
            const int f = h * 8 + d;
            const float e0 = ve0[f], e1 = ve1[f];
            const float o  = acc[d] * invl;
            g_attn[qg * 128 + f] = o * (e1 - e0) + e0;
        }
    }
}

// ---------------- Pass C: output projection (unchanged) ----------------
__global__ __launch_bounds__(256) void out_kernel(
    const float* __restrict__ Wo,
    float* __restrict__ out)
{
    __shared__ float As[16][132];
    __shared__ float Bs[16][68];
    const int m0 = blockIdx.x * 128;
    const int n0 = blockIdx.y * 64;
    const int t  = threadIdx.x;

    const int arow = t >> 1;
    const int akA  = (t & 1) * 4;
    const int brow = t >> 2;
    const int bk   = (t & 3) * 4;
    const float* ar_ = g_attn + (size_t)(m0 + arow) * 128;
    const float* br_ = Wo + (size_t)(n0 + brow) * 128;

    const int tyy = t >> 4, txx = t & 15;
    const int i0 = tyy * 8, j0 = txx * 4;

    float4 a0 = *(const float4*)(ar_ + akA);
    float4 a1 = *(const float4*)(ar_ + akA + 8);
    float4 b0 = *(const float4*)(br_ + bk);

    float acc[8][4] = {};
    for (int k0 = 0; k0 < 128; k0 += 16) {
        __syncthreads();
        As[akA + 0][arow] = a0.x; As[akA + 1][arow] = a0.y;
        As[akA + 2][arow] = a0.z; As[akA + 3][arow] = a0.w;
        As[akA + 8][arow] = a1.x; As[akA + 9][arow] = a1.y;
        As[akA +10][arow] = a1.z; As[akA +11][arow] = a1.w;
        Bs[bk + 0][brow] = b0.x; Bs[bk + 1][brow] = b0.y;
        Bs[bk + 2][brow] = b0.z; Bs[bk + 3][brow] = b0.w;
        __syncthreads();
        if (k0 + 16 < 128) {
            a0 = *(const float4*)(ar_ + k0 + 16 + akA);
            a1 = *(const float4*)(ar_ + k0 + 16 + akA + 8);
            b0 = *(const float4*)(br_ + k0 + 16 + bk);
        }
        #pragma unroll
        for (int kk = 0; kk < 16; ++kk) {
            const float4 av0 = *(const float4*)&As[kk][i0];
            const float4 av1 = *(const float4*)&As[kk][i0 + 4];
            const float4 bv  = *(const float4*)&Bs[kk][j0];
            float ar[8] = {av0.x, av0.y, av0.z, av0.w, av1.x, av1.y, av1.z, av1.w};
            float br[4] = {bv.x, bv.y, bv.z, bv.w};
            #pragma unroll
            for (int i = 0; i < 8; ++i)
                #pragma unroll
                for (int j = 0; j < 4; ++j)
                    acc[i][j] = fmaf(ar[i], br[j], acc[i][j]);
        }
    }
    #pragma unroll
    for (int i = 0; i < 8; ++i) {
        float4 o = make_float4(acc[i][0], acc[i][1], acc[i][2], acc[i][3]);
        *(float4*)&out[(size_t)(m0 + i0 + i) * DMODEL + n0 + j0] = o;
    }
}

// ---------------- launch ----------------
extern "C" void kernel_launch(void* const* d_in, const int* in_sizes, int n_in,
                              void* d_out, int out_size)
{
    const float* X   = (const float*)d_in[0];
    const float* Wq  = (const float*)d_in[1];
    const float* Wk  = (const float*)d_in[2];
    const float* Wv  = (const float*)d_in[3];
    const float* Wo  = (const float*)d_in[4];
    const float* ve0 = (const float*)d_in[5];
    const float* ve1 = (const float*)d_in[6];
    const float* tau = (const float*)d_in[7];
    float* out = (float*)d_out;
    (void)in_sizes; (void)n_in; (void)out_size;

    cudaFuncSetAttribute(attn_kernel,
                         cudaFuncAttributeMaxDynamicSharedMemorySize,
                         SMEM_FLOATS * (int)sizeof(float));

    convert_x <<<4096, 256>>>(X);
    convert_w <<<384, 256>>>(Wq, Wk, Wv);
    proj_mma  <<<dim3(32, 3), 256>>>(tau);
    attn_kernel<<<dim3(32, 16), 256, SMEM_FLOATS * sizeof(float)>>>(tau, ve0, ve1);
    out_kernel <<<dim3(16, 32), 256>>>(Wo, out);
}